// round 15
// baseline (speedup 1.0000x reference)
#include <cuda_runtime.h>
#include <cuda_bf16.h>
#include <cfloat>

// ---------------------------------------------------------------------------
// VectorQuantizer (VQ-VAE) fused pipeline, sm_100.
// R14 -> R15: REVERT the splitK regression (grid back to 256 = R13's 342us
// structure) and remove the global candidate counter -- the contended
// single-word atomicAdd(&g_ncand) whose queueing stalled whole CTAs at each
// chunk barrier (R13 vs R14 contrast: more CTAs -> more contention -> slower).
// New collection: per-row slots (g_crow[row][32], u16) + per-row counters in
// CTA-local smem; overflow (>32, never in practice) marks the row for an
// exact full-scan fallback in rescreen. Rescreen: warp-per-row, exact
// reference-rounded values, in-warp argmin (lowest-index ties), plain store
// to g_best -- zero global atomics in the whole argmin path.
// ---------------------------------------------------------------------------

#define NROWS 32768
#define KN    4096
#define DIM   64

// pass A tiling
#define AM    128            // rows per CTA
#define ABLK  (NROWS / AM)   // 256 CTAs
#define ACH   128            // codes per chunk
#define NACH  (KN / ACH)     // 32
#define LDT   72             // smem tile row stride (halves): conflict-free ldmatrix
#define MARGIN 6e-4f
#define RSLOTS 32            // candidate slots per row

// output offsets (elements)
#define O_ZQ   0
#define O_IND  2097152
#define O_LOSS 2129920
#define O_NE   2129921
#define O_NCS  2392065
#define O_NW   2396161

// scratch
__device__ float              g_zz[NROWS];
__device__ float              g_e2[KN];
__device__ float              g_rmin[NROWS];     // warm-start row min (exact, +slack)
__device__ float              g_counts[KN];
__device__ float              g_dw[KN * DIM];
__device__ float              g_cs[KN];
__device__ float              g_losssum;
__device__ unsigned long long g_best[NROWS];     // (v_bits<<32)|code (plain store)
__device__ unsigned short     g_crow[NROWS * RSLOTS];  // per-row candidate codes
__device__ unsigned           g_candN[NROWS];          // per-row candidate counts
__device__ __nv_bfloat16      g_zb[NROWS * DIM];
__device__ __nv_bfloat16      g_eb[KN * DIM];

__device__ __forceinline__ unsigned smem_u32(const void* p) {
    unsigned r;
    asm("{ .reg .u64 t; cvta.to.shared.u64 t, %1; cvt.u32.u64 %0, t; }"
        : "=r"(r) : "l"(p));
    return r;
}

#define MMA16816(c, A, B0, B1) \
    asm volatile("mma.sync.aligned.m16n8k16.row.col.f32.bf16.bf16.f32 " \
        "{%0,%1,%2,%3}, {%4,%5,%6,%7}, {%8,%9}, {%0,%1,%2,%3};" \
        : "+f"((c)[0]), "+f"((c)[1]), "+f"((c)[2]), "+f"((c)[3]) \
        : "r"((A)[0]), "r"((A)[1]), "r"((A)[2]), "r"((A)[3]), \
          "r"(B0), "r"(B1))

#define CP_ASYNC8(dst, src) \
    asm volatile("cp.async.ca.shared.global [%0], [%1], 8;" \
        :: "r"(dst), "l"(src))

// ---------------------------------------------------------------------------
// K0a: zero g_dw, convert emb->bf16 (vectorized), ||e||^2 (exact reference
// rounding: sequential fadd_rn(fmul_rn), order preserved), counts, globals.
// ---------------------------------------------------------------------------
__global__ void k_prep_a(const float* __restrict__ emb) {
    int i = blockIdx.x * blockDim.x + threadIdx.x;   // 16384 threads
    #pragma unroll
    for (int it = 0; it < 4; it++) {
        int j = i + it * 16384;                      // 65536 uint4/uint2 slots
        ((uint4*)g_dw)[j] = make_uint4(0u, 0u, 0u, 0u);
        float4 v = __ldg((const float4*)emb + j);
        __nv_bfloat162 lo = __float22bfloat162_rn(make_float2(v.x, v.y));
        __nv_bfloat162 hi = __float22bfloat162_rn(make_float2(v.z, v.w));
        uint2 u;
        u.x = *(unsigned*)&lo;
        u.y = *(unsigned*)&hi;
        ((uint2*)g_eb)[j] = u;
    }
    if (i < KN) {
        g_counts[i] = 0.f;
        const float4* e4 = (const float4*)(emb + (size_t)i * DIM);
        float s = 0.f;
        #pragma unroll
        for (int q = 0; q < 16; q++) {
            float4 v = __ldg(e4 + q);
            s = __fadd_rn(s, __fmul_rn(v.x, v.x));
            s = __fadd_rn(s, __fmul_rn(v.y, v.y));
            s = __fadd_rn(s, __fmul_rn(v.z, v.z));
            s = __fadd_rn(s, __fmul_rn(v.w, v.w));
        }
        g_e2[i] = s;
    }
    if (i == 0) g_losssum = 0.f;
}

// ---------------------------------------------------------------------------
// K0b: convert z->bf16 (vectorized), ||z||^2 (sequential rounding).
// ---------------------------------------------------------------------------
__global__ void k_prep_b(const float* __restrict__ z) {
    int i = blockIdx.x * blockDim.x + threadIdx.x;   // 65536 threads
    #pragma unroll
    for (int it = 0; it < 8; it++) {
        int j = i + it * 65536;                      // 524288 float4 slots
        float4 v = __ldg((const float4*)z + j);
        __nv_bfloat162 lo = __float22bfloat162_rn(make_float2(v.x, v.y));
        __nv_bfloat162 hi = __float22bfloat162_rn(make_float2(v.z, v.w));
        uint2 u;
        u.x = *(unsigned*)&lo;
        u.y = *(unsigned*)&hi;
        ((uint2*)g_zb)[j] = u;
    }
    if (i < NROWS) {
        const float4* z4 = (const float4*)(z + (size_t)i * DIM);
        float s = 0.f;
        #pragma unroll
        for (int q = 0; q < 16; q++) {
            float4 v = __ldg(z4 + q);
            s = __fadd_rn(s, __fmul_rn(v.x, v.x));
            s = __fadd_rn(s, __fmul_rn(v.y, v.y));
            s = __fadd_rn(s, __fmul_rn(v.z, v.z));
            s = __fadd_rn(s, __fmul_rn(v.w, v.w));
        }
        g_zz[i] = s;
    }
}

// ---------------------------------------------------------------------------
// K0c: warm-start rowmin. Every row: exact fp32 s'=1+||e||^2-2 z.e over the
// SAME 32 sampled codes (smem-broadcast). +1e-4 slack covers exact-vs-bf16
// crossover at the threshold (guarantees >=1 take per row).
// ---------------------------------------------------------------------------
__global__ void k_warm(const float* __restrict__ z, const float* __restrict__ emb) {
    __shared__ float ec[32 * DIM];   // 8 KB sampled codes
    __shared__ float ee2[32];
    const int tid = threadIdx.x;     // 256
    for (int i = tid; i < 32 * DIM; i += 256) {
        int j = i >> 6, d = i & 63;
        ec[i] = __ldg(&emb[(size_t)(j * 128 + 64) * DIM + d]);
    }
    __syncthreads();
    if (tid < 32) {
        float s = 0.f;
        #pragma unroll
        for (int d = 0; d < DIM; d++) { float v = ec[tid * DIM + d]; s += v * v; }
        ee2[tid] = 1.0f + s;
    }
    __syncthreads();

    int row = blockIdx.x * 256 + tid;
    const float4* zr4 = (const float4*)(z + (size_t)row * DIM);
    float4 zl[16];
    #pragma unroll
    for (int q = 0; q < 16; q++) zl[q] = zr4[q];

    float best = FLT_MAX;
    #pragma unroll 4
    for (int j = 0; j < 32; j++) {
        const float4* e4 = (const float4*)(ec + j * DIM);
        float dot = 0.f;
        #pragma unroll
        for (int q = 0; q < 16; q++) {
            float4 e = e4[q];
            dot = fmaf(zl[q].x, e.x, dot);
            dot = fmaf(zl[q].y, e.y, dot);
            dot = fmaf(zl[q].z, e.z, dot);
            dot = fmaf(zl[q].w, e.w, dot);
        }
        best = fminf(best, fmaf(-2.f, dot, ee2[j]));
    }
    g_rmin[row] = best + 1e-4f;
}

// ---------------------------------------------------------------------------
// K1 (pass A): bf16 mma.sync distance scan + per-row candidate collection.
// Grid 256 (R13 structure). Appends: smem per-row counter atomic + plain
// 2-byte global store -- no global atomics anywhere.
// ---------------------------------------------------------------------------
__global__ void __launch_bounds__(256, 3) k_passA() {
    extern __shared__ __align__(16) char smA[];
    __nv_bfloat16* zt = (__nv_bfloat16*)smA;                  // 9216 halves
    float*    e2s    = (float*)(smA + 55296);                 // 2*128 floats
    unsigned* rowmin = (unsigned*)(smA + 56320);              // 128
    unsigned* cnt    = (unsigned*)(smA + 56832);              // 128

    const int tid  = threadIdx.x;
    const int lane = tid & 31;
    const int w    = tid >> 5;
    const int wm   = w >> 1;        // 0..3
    const int wn   = w & 1;         // 0..1
    const int gid  = lane >> 2;     // fragment row group
    const int qid  = lane & 3;      // fragment col pair
    const int r0   = blockIdx.x * AM;

    // ---- stage z tile (plain, once) ----
    const uint2* zb2 = (const uint2*)g_zb;
    #pragma unroll
    for (int it = 0; it < 8; it++) {
        int i  = tid + it * 256;       // 2048
        int r  = i >> 4;
        int c4 = i & 15;
        *(uint2*)(zt + r * LDT + c4 * 4) = zb2[(size_t)(r0 + r) * 16 + c4];
    }
    if (tid < AM) {
        rowmin[tid] = __float_as_uint(__ldg(&g_rmin[r0 + tid]));
        cnt[tid] = 0u;
    }

    // ---- prefetch e chunk 0 ----
    {
        unsigned etb = smem_u32(zt + 9216);
        const char* src0 = (const char*)g_eb;
        #pragma unroll
        for (int it = 0; it < 8; it++) {
            int i  = tid + it * 256;
            int r  = i >> 4;
            int c4 = i & 15;
            CP_ASYNC8(etb + (unsigned)(r * LDT + c4 * 4) * 2,
                      src0 + ((size_t)r * 64 + c4 * 4) * 2);
        }
        asm volatile("cp.async.commit_group;");
        if (tid < ACH) e2s[tid] = __ldg(&g_e2[tid]) + 1.0f;
    }
    __syncthreads();   // zt + rowmin + cnt visible

    // ---- A fragments (held across all chunks) ----
    unsigned a[2][4][4];
    {
        unsigned ztb = smem_u32(zt);
        #pragma unroll
        for (int tm = 0; tm < 2; tm++)
            #pragma unroll
            for (int kt = 0; kt < 4; kt++) {
                int R0 = wm * 32 + tm * 16;
                unsigned addr = ztb +
                    (unsigned)((R0 + (lane & 15)) * LDT + kt * 16 +
                               ((lane >> 4) << 3)) * 2;
                asm volatile(
                    "ldmatrix.sync.aligned.m8n8.x4.shared.b16 {%0,%1,%2,%3}, [%4];"
                    : "=r"(a[tm][kt][0]), "=r"(a[tm][kt][1]),
                      "=r"(a[tm][kt][2]), "=r"(a[tm][kt][3])
                    : "r"(addr));
            }
    }

    // thread's 4 row slots: slot = tm*2 + jh -> rl = wm*32 + tm*16 + gid + jh*8
    int rls[4];
    #pragma unroll
    for (int slot = 0; slot < 4; slot++)
        rls[slot] = wm * 32 + (slot >> 1) * 16 + gid + (slot & 1) * 8;

    for (int ch = 0; ch < NACH; ch++) {
        asm volatile("cp.async.wait_group 0;");
        __syncthreads();   // current et/e2s visible; prev epilogue done

        if (ch + 1 < NACH) {
            int nb2 = (ch + 1) & 1;
            unsigned etb = smem_u32(zt + 9216 + nb2 * 9216);
            const char* src = (const char*)g_eb +
                              (size_t)(ch + 1) * ACH * 64 * 2;
            #pragma unroll
            for (int it = 0; it < 8; it++) {
                int i  = tid + it * 256;
                int r  = i >> 4;
                int c4 = i & 15;
                CP_ASYNC8(etb + (unsigned)(r * LDT + c4 * 4) * 2,
                          src + ((size_t)r * 64 + c4 * 4) * 2);
            }
            asm volatile("cp.async.commit_group;");
            if (tid < ACH)
                e2s[nb2 * ACH + tid] = __ldg(&g_e2[(ch + 1) * ACH + tid]) + 1.0f;
        }

        // per-chunk thresholds (stale-read safe: only over-collects)
        float thr[4], lmin[4];
        #pragma unroll
        for (int slot = 0; slot < 4; slot++) {
            thr[slot]  = __uint_as_float(rowmin[rls[slot]]) + MARGIN;
            lmin[slot] = FLT_MAX;
        }

        const int cb = ch & 1;
        unsigned et_base = smem_u32(zt + 9216 + cb * 9216);
        const float* e2c = e2s + cb * ACH;

        #pragma unroll
        for (int nt = 0; nt < 8; nt++) {
            const int nb = wn * 64 + nt * 8;

            unsigned b0[4], b1[4];
            #pragma unroll
            for (int kt = 0; kt < 4; kt++) {
                unsigned addr = et_base +
                    (unsigned)((nb + (lane & 7)) * LDT + kt * 16 +
                               (((lane >> 3) & 1) << 3)) * 2;
                asm volatile(
                    "ldmatrix.sync.aligned.m8n8.x2.shared.b16 {%0,%1}, [%2];"
                    : "=r"(b0[kt]), "=r"(b1[kt]) : "r"(addr));
            }

            float c0[4] = {0.f, 0.f, 0.f, 0.f};
            float c1[4] = {0.f, 0.f, 0.f, 0.f};
            #pragma unroll
            for (int kt = 0; kt < 4; kt++) {
                MMA16816(c0, a[0][kt], b0[kt], b1[kt]);
                MMA16816(c1, a[1][kt], b0[kt], b1[kt]);
            }

            const float e2p0 = e2c[nb + qid * 2];
            const float e2p1 = e2c[nb + qid * 2 + 1];

            #pragma unroll
            for (int tm = 0; tm < 2; tm++) {
                const float* cc = tm ? c1 : c0;
                #pragma unroll
                for (int jh = 0; jh < 2; jh++) {
                    int slot = tm * 2 + jh;
                    float s0 = fmaf(-2.f, cc[jh * 2],     e2p0);
                    float s1 = fmaf(-2.f, cc[jh * 2 + 1], e2p1);
                    float m2 = fminf(s0, s1);
                    lmin[slot] = fminf(lmin[slot], m2);
                    if (m2 <= thr[slot]) {                  // rare
                        int rl = rls[slot];
                        unsigned codeb = (unsigned)(ch * ACH + nb + qid * 2);
                        if (s0 <= thr[slot]) {
                            unsigned j = atomicAdd(&cnt[rl], 1u);
                            if (j < RSLOTS)
                                g_crow[(size_t)(r0 + rl) * RSLOTS + j] =
                                    (unsigned short)codeb;
                        }
                        if (s1 <= thr[slot]) {
                            unsigned j = atomicAdd(&cnt[rl], 1u);
                            if (j < RSLOTS)
                                g_crow[(size_t)(r0 + rl) * RSLOTS + j] =
                                    (unsigned short)(codeb + 1);
                        }
                    }
                }
            }
        }

        // fold chunk minima into shared rowmin (visible next chunk via sync)
        #pragma unroll
        for (int slot = 0; slot < 4; slot++)
            atomicMin(&rowmin[rls[slot]], __float_as_uint(lmin[slot]));
    }

    __syncthreads();
    if (tid < AM) g_candN[r0 + tid] = cnt[tid];
}

// ---------------------------------------------------------------------------
// K2 (pass B): exact reference-rounded rescreen, WARP PER ROW, no atomics.
// 8-lane groups evaluate up to 4 candidates/iteration; in-warp argmin with
// exact value order + lowest-index tie-break; g_best written by lane 0.
// Overflow rows (cnt > RSLOTS; never in practice) fall back to an exact
// full scan over all 4096 codes.
// v = fsub_rn(fadd_rn(zz,ee), 2*dot), dot assoc safe (ulp(64) grid argument,
// empirically bit-stable R8->R13).
// ---------------------------------------------------------------------------
__global__ void k_rescreen(const float* __restrict__ z,
                           const float* __restrict__ emb) {
    const int row = blockIdx.x * 8 + (threadIdx.x >> 5);
    const int ln  = threadIdx.x & 31;
    const int sub = ln >> 3;
    const int sl  = ln & 7;
    const unsigned gmask = 0xFFu << (sub * 8);

    const float zz = __ldg(&g_zz[row]);
    const float4* zr = (const float4*)(z + (size_t)row * DIM);
    float4 za = __ldg(zr + sl * 2), zb = __ldg(zr + sl * 2 + 1);

    float bv = FLT_MAX;
    int   bc = 0x7fffffff;

    unsigned c = g_candN[row];
    if (c <= RSLOTS) {
        for (unsigned base = 0; base < c; base += 4) {
            unsigned i = base + (unsigned)sub;
            bool ok = i < c;
            int code = ok ? (int)__ldg(&g_crow[(size_t)row * RSLOTS + i]) : 0;
            const float4* er = (const float4*)(emb + (size_t)code * DIM) + sl * 2;
            float4 e0 = __ldg(er), e1 = __ldg(er + 1);
            float p = __fmul_rn(za.x, e0.x);
            p = __fmaf_rn(za.y, e0.y, p);
            p = __fmaf_rn(za.z, e0.z, p);
            p = __fmaf_rn(za.w, e0.w, p);
            p = __fmaf_rn(zb.x, e1.x, p);
            p = __fmaf_rn(zb.y, e1.y, p);
            p = __fmaf_rn(zb.z, e1.z, p);
            p = __fmaf_rn(zb.w, e1.w, p);
            p += __shfl_xor_sync(gmask, p, 1);
            p += __shfl_xor_sync(gmask, p, 2);
            p += __shfl_xor_sync(gmask, p, 4);
            if (sl == 0 && ok) {
                float v = __fsub_rn(__fadd_rn(zz, __ldg(&g_e2[code])),
                                    __fmul_rn(2.f, p));
                if (v < bv || (v == bv && code < bc)) { bv = v; bc = code; }
            }
        }
    } else {
        // overflow safety net: exact scan of all codes (sequential dot per
        // code, reference rounding). Practically unreachable.
        const float* zrow = z + (size_t)row * DIM;
        for (int code = ln; code < KN; code += 32) {
            const float* er = emb + (size_t)code * DIM;
            float acc = 0.f;
            #pragma unroll
            for (int d = 0; d < DIM; d++)
                acc = __fmaf_rn(zrow[d], __ldg(er + d), acc);
            float v = __fsub_rn(__fadd_rn(zz, __ldg(&g_e2[code])),
                                __fmul_rn(2.f, acc));
            if (v < bv || (v == bv && code < bc)) { bv = v; bc = code; }
        }
    }

    // full-warp (v, code) argmin reduction; non-leader lanes hold FLT_MAX
    #pragma unroll
    for (int o = 16; o; o >>= 1) {
        float ov = __shfl_xor_sync(0xffffffffu, bv, o);
        int   oc = __shfl_xor_sync(0xffffffffu, bc, o);
        if (ov < bv || (ov == bv && oc < bc)) { bv = ov; bc = oc; }
    }
    if (ln == 0)
        g_best[row] = ((unsigned long long)__float_as_uint(bv) << 32) |
                      (unsigned)bc;
}

// ---------------------------------------------------------------------------
// K3: gather z_q, straight-through output, loss partial, scatter counts/dw.
// ---------------------------------------------------------------------------
__global__ void k_scatter(const float* __restrict__ z, const float* __restrict__ emb,
                          float* __restrict__ out)
{
    int row = blockIdx.x * 8 + (threadIdx.x >> 5);
    int ln  = threadIdx.x & 31;
    int idx = (int)(unsigned)(g_best[row] & 0xffffffffull);
    const float* zr = z   + (size_t)row * DIM;
    const float* er = emb + (size_t)idx * DIM;
    float* zq = out + O_ZQ + (size_t)row * DIM;
    float l = 0.f;
    #pragma unroll
    for (int t = 0; t < 2; t++) {
        int j = ln + 32 * t;
        float zv = zr[j], ev = __ldg(er + j);
        zq[j] = __fadd_rn(zv, __fsub_rn(ev, zv));
        float dd = __fsub_rn(zv, ev);
        l += dd * dd;
        atomicAdd(&g_dw[idx * DIM + j], zv);
    }
    if (ln == 0) {
        atomicAdd(&g_counts[idx], 1.f);
        out[O_IND + row] = (float)idx;
    }
    #pragma unroll
    for (int o = 16; o; o >>= 1) l += __shfl_xor_sync(0xffffffffu, l, o);
    __shared__ float sl2[8];
    if (ln == 0) sl2[threadIdx.x >> 5] = l;
    __syncthreads();
    if (threadIdx.x == 0) {
        float s = 0.f;
        #pragma unroll
        for (int w2 = 0; w2 < 8; w2++) s += sl2[w2];
        atomicAdd(&g_losssum, s);
    }
}

// ---------------------------------------------------------------------------
// K4: new_cluster_size, n, normalized cluster size, loss (single block)
// ---------------------------------------------------------------------------
__global__ void k_fin1(const float* __restrict__ ema_cs, float* __restrict__ out)
{
    int tid = threadIdx.x;  // 1024
    float ncs[4];
    float s = 0.f;
    #pragma unroll
    for (int j = 0; j < 4; j++) {
        int k = tid + j * 1024;
        float v = 0.99f * ema_cs[k] + 0.01f * g_counts[k];
        ncs[j] = v; s += v;
        out[O_NCS + k] = v;
    }
    __shared__ float sp[32];
    #pragma unroll
    for (int o = 16; o; o >>= 1) s += __shfl_xor_sync(0xffffffffu, s, o);
    if ((tid & 31) == 0) sp[tid >> 5] = s;
    __syncthreads();
    if (tid < 32) {
        float v = sp[tid];
        #pragma unroll
        for (int o = 16; o; o >>= 1) v += __shfl_xor_sync(0xffffffffu, v, o);
        if (tid == 0) sp[0] = v;
    }
    __syncthreads();
    float n = sp[0];
    float denom = n + (float)KN * 1e-5f;
    #pragma unroll
    for (int j = 0; j < 4; j++) {
        int k = tid + j * 1024;
        g_cs[k] = (ncs[j] + 1e-5f) / denom * n;
    }
    if (tid == 0) out[O_LOSS] = 0.25f * (g_losssum / 2097152.0f);
}

// ---------------------------------------------------------------------------
// K5: new_ema_w and new_embedding
// ---------------------------------------------------------------------------
__global__ void k_fin2(const float* __restrict__ ema_w, float* __restrict__ out)
{
    int i = blockIdx.x * blockDim.x + threadIdx.x;   // 262144 total
    float nw = 0.99f * ema_w[i] + 0.01f * g_dw[i];
    out[O_NW + i] = nw;
    out[O_NE + i] = __fdiv_rn(nw, g_cs[i >> 6]);
}

// ---------------------------------------------------------------------------
#define SMA_BYTES 57344

extern "C" void kernel_launch(void* const* d_in, const int* in_sizes, int n_in,
                              void* d_out, int out_size)
{
    const float* z      = (const float*)d_in[0];
    const float* emb    = (const float*)d_in[1];
    const float* ema_cs = (const float*)d_in[2];
    const float* ema_w  = (const float*)d_in[3];
    float* out = (float*)d_out;

    cudaFuncSetAttribute(k_passA, cudaFuncAttributeMaxDynamicSharedMemorySize,
                         SMA_BYTES);

    k_prep_a  <<<64, 256>>>(emb);                 // launch 0
    k_prep_b  <<<256, 256>>>(z);                  // launch 1
    k_warm    <<<NROWS / 256, 256>>>(z, emb);     // launch 2
    k_passA   <<<ABLK, 256, SMA_BYTES>>>();       // launch 3  <- profiled
    k_rescreen<<<NROWS / 8, 256>>>(z, emb);       // launch 4
    k_scatter <<<NROWS / 8, 256>>>(z, emb, out);  // launch 5
    k_fin1    <<<1, 1024>>>(ema_cs, out);         // launch 6
    k_fin2    <<<KN * DIM / 256, 256>>>(ema_w, out); // launch 7
}

// round 17
// speedup vs baseline: 1.0089x; 1.0089x over previous
#include <cuda_runtime.h>
#include <cuda_bf16.h>
#include <cfloat>

// ---------------------------------------------------------------------------
// VectorQuantizer (VQ-VAE) fused pipeline, sm_100.
// (Round-17 resubmit: R16 never ran -- broker container failed twice, 5th
//  infra failure this session; failure precedes compile, uncorrelated with
//  source. Identical kernel so the R16 prediction gets measured.)
// R15 -> R16/R17: passA's 105us confirmed (global-atomic removal was right);
// the 1700us R15 regression was the warm SAMPLE CODES taking themselves (32
// forced takes/row -> cnt>RSLOTS -> full-scan fallback on ~every row). Fix:
//   - passA excludes sample codes from collection ((nb+qid*2)==64 compare)
//   - k_warm records g_wcode = argmin over samples on the EXACT
//     reference-rounded values (lowest-index ties); rescreen appends it as
//     an extra candidate, so a sample winner is always covered.
// Everything else identical to R15 (passA 105us structure, warp-per-row
// rescreen, no global atomics in the argmin path).
// ---------------------------------------------------------------------------

#define NROWS 32768
#define KN    4096
#define DIM   64

// pass A tiling
#define AM    128            // rows per CTA
#define ABLK  (NROWS / AM)   // 256 CTAs
#define ACH   128            // codes per chunk
#define NACH  (KN / ACH)     // 32
#define LDT   72             // smem tile row stride (halves): conflict-free ldmatrix
#define MARGIN 6e-4f
#define RSLOTS 32            // candidate slots per row

// output offsets (elements)
#define O_ZQ   0
#define O_IND  2097152
#define O_LOSS 2129920
#define O_NE   2129921
#define O_NCS  2392065
#define O_NW   2396161

// scratch
__device__ float              g_zz[NROWS];
__device__ float              g_e2[KN];
__device__ float              g_rmin[NROWS];     // warm-start row min (exact, +slack)
__device__ int                g_wcode[NROWS];    // best sample code (ref-rounded, low-idx ties)
__device__ float              g_counts[KN];
__device__ float              g_dw[KN * DIM];
__device__ float              g_cs[KN];
__device__ float              g_losssum;
__device__ unsigned long long g_best[NROWS];     // (v_bits<<32)|code (plain store)
__device__ unsigned short     g_crow[NROWS * RSLOTS];  // per-row candidate codes
__device__ unsigned           g_candN[NROWS];          // per-row candidate counts
__device__ __nv_bfloat16      g_zb[NROWS * DIM];
__device__ __nv_bfloat16      g_eb[KN * DIM];

__device__ __forceinline__ unsigned smem_u32(const void* p) {
    unsigned r;
    asm("{ .reg .u64 t; cvta.to.shared.u64 t, %1; cvt.u32.u64 %0, t; }"
        : "=r"(r) : "l"(p));
    return r;
}

#define MMA16816(c, A, B0, B1) \
    asm volatile("mma.sync.aligned.m16n8k16.row.col.f32.bf16.bf16.f32 " \
        "{%0,%1,%2,%3}, {%4,%5,%6,%7}, {%8,%9}, {%0,%1,%2,%3};" \
        : "+f"((c)[0]), "+f"((c)[1]), "+f"((c)[2]), "+f"((c)[3]) \
        : "r"((A)[0]), "r"((A)[1]), "r"((A)[2]), "r"((A)[3]), \
          "r"(B0), "r"(B1))

#define CP_ASYNC8(dst, src) \
    asm volatile("cp.async.ca.shared.global [%0], [%1], 8;" \
        :: "r"(dst), "l"(src))

// ---------------------------------------------------------------------------
// K0a: zero g_dw, convert emb->bf16 (vectorized), ||e||^2 (exact reference
// rounding: sequential fadd_rn(fmul_rn), order preserved), counts, globals.
// ---------------------------------------------------------------------------
__global__ void k_prep_a(const float* __restrict__ emb) {
    int i = blockIdx.x * blockDim.x + threadIdx.x;   // 16384 threads
    #pragma unroll
    for (int it = 0; it < 4; it++) {
        int j = i + it * 16384;                      // 65536 uint4/uint2 slots
        ((uint4*)g_dw)[j] = make_uint4(0u, 0u, 0u, 0u);
        float4 v = __ldg((const float4*)emb + j);
        __nv_bfloat162 lo = __float22bfloat162_rn(make_float2(v.x, v.y));
        __nv_bfloat162 hi = __float22bfloat162_rn(make_float2(v.z, v.w));
        uint2 u;
        u.x = *(unsigned*)&lo;
        u.y = *(unsigned*)&hi;
        ((uint2*)g_eb)[j] = u;
    }
    if (i < KN) {
        g_counts[i] = 0.f;
        const float4* e4 = (const float4*)(emb + (size_t)i * DIM);
        float s = 0.f;
        #pragma unroll
        for (int q = 0; q < 16; q++) {
            float4 v = __ldg(e4 + q);
            s = __fadd_rn(s, __fmul_rn(v.x, v.x));
            s = __fadd_rn(s, __fmul_rn(v.y, v.y));
            s = __fadd_rn(s, __fmul_rn(v.z, v.z));
            s = __fadd_rn(s, __fmul_rn(v.w, v.w));
        }
        g_e2[i] = s;
    }
    if (i == 0) g_losssum = 0.f;
}

// ---------------------------------------------------------------------------
// K0b: convert z->bf16 (vectorized), ||z||^2 (sequential rounding).
// ---------------------------------------------------------------------------
__global__ void k_prep_b(const float* __restrict__ z) {
    int i = blockIdx.x * blockDim.x + threadIdx.x;   // 65536 threads
    #pragma unroll
    for (int it = 0; it < 8; it++) {
        int j = i + it * 65536;                      // 524288 float4 slots
        float4 v = __ldg((const float4*)z + j);
        __nv_bfloat162 lo = __float22bfloat162_rn(make_float2(v.x, v.y));
        __nv_bfloat162 hi = __float22bfloat162_rn(make_float2(v.z, v.w));
        uint2 u;
        u.x = *(unsigned*)&lo;
        u.y = *(unsigned*)&hi;
        ((uint2*)g_zb)[j] = u;
    }
    if (i < NROWS) {
        const float4* z4 = (const float4*)(z + (size_t)i * DIM);
        float s = 0.f;
        #pragma unroll
        for (int q = 0; q < 16; q++) {
            float4 v = __ldg(z4 + q);
            s = __fadd_rn(s, __fmul_rn(v.x, v.x));
            s = __fadd_rn(s, __fmul_rn(v.y, v.y));
            s = __fadd_rn(s, __fmul_rn(v.z, v.z));
            s = __fadd_rn(s, __fmul_rn(v.w, v.w));
        }
        g_zz[i] = s;
    }
}

// ---------------------------------------------------------------------------
// K0c: warm-start. Per row over the SAME 32 sampled codes (j*128+64):
//   - g_rmin  = min(1 + e2 - 2 dot) + 1e-4 slack   (passA threshold scale)
//   - g_wcode = argmin of the EXACT reference-rounded
//               v = fsub_rn(fadd_rn(zz, e2), 2*dot)  (lowest-index ties)
// If the global winner is a sample, it is the sample min, so g_wcode covers
// it; passA excludes samples from collection.
// ---------------------------------------------------------------------------
__global__ void k_warm(const float* __restrict__ z, const float* __restrict__ emb) {
    __shared__ float ec[32 * DIM];   // 8 KB sampled codes
    __shared__ float ee2[32];        // exact g_e2 of samples
    const int tid = threadIdx.x;     // 256
    for (int i = tid; i < 32 * DIM; i += 256) {
        int j = i >> 6, d = i & 63;
        ec[i] = __ldg(&emb[(size_t)(j * 128 + 64) * DIM + d]);
    }
    if (tid < 32) ee2[tid] = __ldg(&g_e2[tid * 128 + 64]);
    __syncthreads();

    int row = blockIdx.x * 256 + tid;
    const float zz = __ldg(&g_zz[row]);
    const float4* zr4 = (const float4*)(z + (size_t)row * DIM);
    float4 zl[16];
    #pragma unroll
    for (int q = 0; q < 16; q++) zl[q] = zr4[q];

    float bestS = FLT_MAX;   // threshold scale: 1 + e2 - 2 dot
    float bestV = FLT_MAX;   // reference-rounded value
    int   bestC = 0;
    #pragma unroll 4
    for (int j = 0; j < 32; j++) {
        const float4* e4 = (const float4*)(ec + j * DIM);
        float dot = 0.f;
        #pragma unroll
        for (int q = 0; q < 16; q++) {
            float4 e = e4[q];
            dot = fmaf(zl[q].x, e.x, dot);
            dot = fmaf(zl[q].y, e.y, dot);
            dot = fmaf(zl[q].z, e.z, dot);
            dot = fmaf(zl[q].w, e.w, dot);
        }
        float e2v = ee2[j];
        bestS = fminf(bestS, fmaf(-2.f, dot, 1.0f + e2v));
        float v = __fsub_rn(__fadd_rn(zz, e2v), __fmul_rn(2.f, dot));
        if (v < bestV) { bestV = v; bestC = j * 128 + 64; }  // ascending j -> low idx
    }
    g_rmin[row]  = bestS + 1e-4f;
    g_wcode[row] = bestC;
}

// ---------------------------------------------------------------------------
// K1 (pass A): bf16 mma.sync distance scan + per-row candidate collection.
// Grid 256. Appends: smem per-row counter atomic + plain 2-byte store.
// Sample codes ((nb + qid*2) == 64, even element only) are NOT collected --
// they are covered by g_wcode in rescreen.
// ---------------------------------------------------------------------------
__global__ void __launch_bounds__(256, 3) k_passA() {
    extern __shared__ __align__(16) char smA[];
    __nv_bfloat16* zt = (__nv_bfloat16*)smA;                  // 9216 halves
    float*    e2s    = (float*)(smA + 55296);                 // 2*128 floats
    unsigned* rowmin = (unsigned*)(smA + 56320);              // 128
    unsigned* cnt    = (unsigned*)(smA + 56832);              // 128

    const int tid  = threadIdx.x;
    const int lane = tid & 31;
    const int w    = tid >> 5;
    const int wm   = w >> 1;        // 0..3
    const int wn   = w & 1;         // 0..1
    const int gid  = lane >> 2;     // fragment row group
    const int qid  = lane & 3;      // fragment col pair
    const int r0   = blockIdx.x * AM;

    // ---- stage z tile (plain, once) ----
    const uint2* zb2 = (const uint2*)g_zb;
    #pragma unroll
    for (int it = 0; it < 8; it++) {
        int i  = tid + it * 256;       // 2048
        int r  = i >> 4;
        int c4 = i & 15;
        *(uint2*)(zt + r * LDT + c4 * 4) = zb2[(size_t)(r0 + r) * 16 + c4];
    }
    if (tid < AM) {
        rowmin[tid] = __float_as_uint(__ldg(&g_rmin[r0 + tid]));
        cnt[tid] = 0u;
    }

    // ---- prefetch e chunk 0 ----
    {
        unsigned etb = smem_u32(zt + 9216);
        const char* src0 = (const char*)g_eb;
        #pragma unroll
        for (int it = 0; it < 8; it++) {
            int i  = tid + it * 256;
            int r  = i >> 4;
            int c4 = i & 15;
            CP_ASYNC8(etb + (unsigned)(r * LDT + c4 * 4) * 2,
                      src0 + ((size_t)r * 64 + c4 * 4) * 2);
        }
        asm volatile("cp.async.commit_group;");
        if (tid < ACH) e2s[tid] = __ldg(&g_e2[tid]) + 1.0f;
    }
    __syncthreads();   // zt + rowmin + cnt visible

    // ---- A fragments (held across all chunks) ----
    unsigned a[2][4][4];
    {
        unsigned ztb = smem_u32(zt);
        #pragma unroll
        for (int tm = 0; tm < 2; tm++)
            #pragma unroll
            for (int kt = 0; kt < 4; kt++) {
                int R0 = wm * 32 + tm * 16;
                unsigned addr = ztb +
                    (unsigned)((R0 + (lane & 15)) * LDT + kt * 16 +
                               ((lane >> 4) << 3)) * 2;
                asm volatile(
                    "ldmatrix.sync.aligned.m8n8.x4.shared.b16 {%0,%1,%2,%3}, [%4];"
                    : "=r"(a[tm][kt][0]), "=r"(a[tm][kt][1]),
                      "=r"(a[tm][kt][2]), "=r"(a[tm][kt][3])
                    : "r"(addr));
            }
    }

    // thread's 4 row slots: slot = tm*2 + jh -> rl = wm*32 + tm*16 + gid + jh*8
    int rls[4];
    #pragma unroll
    for (int slot = 0; slot < 4; slot++)
        rls[slot] = wm * 32 + (slot >> 1) * 16 + gid + (slot & 1) * 8;

    for (int ch = 0; ch < NACH; ch++) {
        asm volatile("cp.async.wait_group 0;");
        __syncthreads();   // current et/e2s visible; prev epilogue done

        if (ch + 1 < NACH) {
            int nb2 = (ch + 1) & 1;
            unsigned etb = smem_u32(zt + 9216 + nb2 * 9216);
            const char* src = (const char*)g_eb +
                              (size_t)(ch + 1) * ACH * 64 * 2;
            #pragma unroll
            for (int it = 0; it < 8; it++) {
                int i  = tid + it * 256;
                int r  = i >> 4;
                int c4 = i & 15;
                CP_ASYNC8(etb + (unsigned)(r * LDT + c4 * 4) * 2,
                          src + ((size_t)r * 64 + c4 * 4) * 2);
            }
            asm volatile("cp.async.commit_group;");
            if (tid < ACH)
                e2s[nb2 * ACH + tid] = __ldg(&g_e2[(ch + 1) * ACH + tid]) + 1.0f;
        }

        // per-chunk thresholds (stale-read safe: only over-collects)
        float thr[4], lmin[4];
        #pragma unroll
        for (int slot = 0; slot < 4; slot++) {
            thr[slot]  = __uint_as_float(rowmin[rls[slot]]) + MARGIN;
            lmin[slot] = FLT_MAX;
        }

        const int cb = ch & 1;
        unsigned et_base = smem_u32(zt + 9216 + cb * 9216);
        const float* e2c = e2s + cb * ACH;

        #pragma unroll
        for (int nt = 0; nt < 8; nt++) {
            const int nb = wn * 64 + nt * 8;
            const bool sample0 = (nb + qid * 2) == 64;   // chunk's sample code

            unsigned b0[4], b1[4];
            #pragma unroll
            for (int kt = 0; kt < 4; kt++) {
                unsigned addr = et_base +
                    (unsigned)((nb + (lane & 7)) * LDT + kt * 16 +
                               (((lane >> 3) & 1) << 3)) * 2;
                asm volatile(
                    "ldmatrix.sync.aligned.m8n8.x2.shared.b16 {%0,%1}, [%2];"
                    : "=r"(b0[kt]), "=r"(b1[kt]) : "r"(addr));
            }

            float c0[4] = {0.f, 0.f, 0.f, 0.f};
            float c1[4] = {0.f, 0.f, 0.f, 0.f};
            #pragma unroll
            for (int kt = 0; kt < 4; kt++) {
                MMA16816(c0, a[0][kt], b0[kt], b1[kt]);
                MMA16816(c1, a[1][kt], b0[kt], b1[kt]);
            }

            const float e2p0 = e2c[nb + qid * 2];
            const float e2p1 = e2c[nb + qid * 2 + 1];

            #pragma unroll
            for (int tm = 0; tm < 2; tm++) {
                const float* cc = tm ? c1 : c0;
                #pragma unroll
                for (int jh = 0; jh < 2; jh++) {
                    int slot = tm * 2 + jh;
                    float s0 = fmaf(-2.f, cc[jh * 2],     e2p0);
                    float s1 = fmaf(-2.f, cc[jh * 2 + 1], e2p1);
                    float m2 = fminf(s0, s1);
                    lmin[slot] = fminf(lmin[slot], m2);
                    if (m2 <= thr[slot]) {                  // rare
                        int rl = rls[slot];
                        unsigned codeb = (unsigned)(ch * ACH + nb + qid * 2);
                        if (s0 <= thr[slot] && !sample0) {
                            unsigned j = atomicAdd(&cnt[rl], 1u);
                            if (j < RSLOTS)
                                g_crow[(size_t)(r0 + rl) * RSLOTS + j] =
                                    (unsigned short)codeb;
                        }
                        if (s1 <= thr[slot]) {              // odd: never a sample
                            unsigned j = atomicAdd(&cnt[rl], 1u);
                            if (j < RSLOTS)
                                g_crow[(size_t)(r0 + rl) * RSLOTS + j] =
                                    (unsigned short)(codeb + 1);
                        }
                    }
                }
            }
        }

        // fold chunk minima into shared rowmin (visible next chunk via sync)
        #pragma unroll
        for (int slot = 0; slot < 4; slot++)
            atomicMin(&rowmin[rls[slot]], __float_as_uint(lmin[slot]));
    }

    __syncthreads();
    if (tid < AM) g_candN[r0 + tid] = cnt[tid];
}

// ---------------------------------------------------------------------------
// K2 (pass B): exact reference-rounded rescreen, WARP PER ROW, no atomics.
// Candidates = stored (cnt) + g_wcode appended as index cnt. 8-lane groups,
// in-warp argmin (exact value order + lowest-index ties), plain store.
// Overflow rows (cnt > RSLOTS; unreachable) fall back to exact full scan.
// ---------------------------------------------------------------------------
__global__ void k_rescreen(const float* __restrict__ z,
                           const float* __restrict__ emb) {
    const int row = blockIdx.x * 8 + (threadIdx.x >> 5);
    const int ln  = threadIdx.x & 31;
    const int sub = ln >> 3;
    const int sl  = ln & 7;
    const unsigned gmask = 0xFFu << (sub * 8);

    const float zz = __ldg(&g_zz[row]);
    const float4* zr = (const float4*)(z + (size_t)row * DIM);
    float4 za = __ldg(zr + sl * 2), zb = __ldg(zr + sl * 2 + 1);

    float bv = FLT_MAX;
    int   bc = 0x7fffffff;

    unsigned c = g_candN[row];
    if (c <= RSLOTS) {
        int wc = __ldg(&g_wcode[row]);
        unsigned total = c + 1;                 // stored + sample-best
        for (unsigned base = 0; base < total; base += 4) {
            unsigned i = base + (unsigned)sub;
            bool ok = i < total;
            int code = 0;
            if (ok)
                code = (i < c) ? (int)__ldg(&g_crow[(size_t)row * RSLOTS + i])
                               : wc;
            const float4* er = (const float4*)(emb + (size_t)code * DIM) + sl * 2;
            float4 e0 = __ldg(er), e1 = __ldg(er + 1);
            float p = __fmul_rn(za.x, e0.x);
            p = __fmaf_rn(za.y, e0.y, p);
            p = __fmaf_rn(za.z, e0.z, p);
            p = __fmaf_rn(za.w, e0.w, p);
            p = __fmaf_rn(zb.x, e1.x, p);
            p = __fmaf_rn(zb.y, e1.y, p);
            p = __fmaf_rn(zb.z, e1.z, p);
            p = __fmaf_rn(zb.w, e1.w, p);
            p += __shfl_xor_sync(gmask, p, 1);
            p += __shfl_xor_sync(gmask, p, 2);
            p += __shfl_xor_sync(gmask, p, 4);
            if (sl == 0 && ok) {
                float v = __fsub_rn(__fadd_rn(zz, __ldg(&g_e2[code])),
                                    __fmul_rn(2.f, p));
                if (v < bv || (v == bv && code < bc)) { bv = v; bc = code; }
            }
        }
    } else {
        // overflow safety net: exact scan of all codes. Practically unreachable.
        const float* zrow = z + (size_t)row * DIM;
        for (int code = ln; code < KN; code += 32) {
            const float* er = emb + (size_t)code * DIM;
            float acc = 0.f;
            #pragma unroll
            for (int d = 0; d < DIM; d++)
                acc = __fmaf_rn(zrow[d], __ldg(er + d), acc);
            float v = __fsub_rn(__fadd_rn(zz, __ldg(&g_e2[code])),
                                __fmul_rn(2.f, acc));
            if (v < bv || (v == bv && code < bc)) { bv = v; bc = code; }
        }
    }

    // full-warp (v, code) argmin reduction; non-leader lanes hold FLT_MAX
    #pragma unroll
    for (int o = 16; o; o >>= 1) {
        float ov = __shfl_xor_sync(0xffffffffu, bv, o);
        int   oc = __shfl_xor_sync(0xffffffffu, bc, o);
        if (ov < bv || (ov == bv && oc < bc)) { bv = ov; bc = oc; }
    }
    if (ln == 0)
        g_best[row] = ((unsigned long long)__float_as_uint(bv) << 32) |
                      (unsigned)bc;
}

// ---------------------------------------------------------------------------
// K3: gather z_q, straight-through output, loss partial, scatter counts/dw.
// ---------------------------------------------------------------------------
__global__ void k_scatter(const float* __restrict__ z, const float* __restrict__ emb,
                          float* __restrict__ out)
{
    int row = blockIdx.x * 8 + (threadIdx.x >> 5);
    int ln  = threadIdx.x & 31;
    int idx = (int)(unsigned)(g_best[row] & 0xffffffffull);
    const float* zr = z   + (size_t)row * DIM;
    const float* er = emb + (size_t)idx * DIM;
    float* zq = out + O_ZQ + (size_t)row * DIM;
    float l = 0.f;
    #pragma unroll
    for (int t = 0; t < 2; t++) {
        int j = ln + 32 * t;
        float zv = zr[j], ev = __ldg(er + j);
        zq[j] = __fadd_rn(zv, __fsub_rn(ev, zv));
        float dd = __fsub_rn(zv, ev);
        l += dd * dd;
        atomicAdd(&g_dw[idx * DIM + j], zv);
    }
    if (ln == 0) {
        atomicAdd(&g_counts[idx], 1.f);
        out[O_IND + row] = (float)idx;
    }
    #pragma unroll
    for (int o = 16; o; o >>= 1) l += __shfl_xor_sync(0xffffffffu, l, o);
    __shared__ float sl2[8];
    if (ln == 0) sl2[threadIdx.x >> 5] = l;
    __syncthreads();
    if (threadIdx.x == 0) {
        float s = 0.f;
        #pragma unroll
        for (int w2 = 0; w2 < 8; w2++) s += sl2[w2];
        atomicAdd(&g_losssum, s);
    }
}

// ---------------------------------------------------------------------------
// K4: new_cluster_size, n, normalized cluster size, loss (single block)
// ---------------------------------------------------------------------------
__global__ void k_fin1(const float* __restrict__ ema_cs, float* __restrict__ out)
{
    int tid = threadIdx.x;  // 1024
    float ncs[4];
    float s = 0.f;
    #pragma unroll
    for (int j = 0; j < 4; j++) {
        int k = tid + j * 1024;
        float v = 0.99f * ema_cs[k] + 0.01f * g_counts[k];
        ncs[j] = v; s += v;
        out[O_NCS + k] = v;
    }
    __shared__ float sp[32];
    #pragma unroll
    for (int o = 16; o; o >>= 1) s += __shfl_xor_sync(0xffffffffu, s, o);
    if ((tid & 31) == 0) sp[tid >> 5] = s;
    __syncthreads();
    if (tid < 32) {
        float v = sp[tid];
        #pragma unroll
        for (int o = 16; o; o >>= 1) v += __shfl_xor_sync(0xffffffffu, v, o);
        if (tid == 0) sp[0] = v;
    }
    __syncthreads();
    float n = sp[0];
    float denom = n + (float)KN * 1e-5f;
    #pragma unroll
    for (int j = 0; j < 4; j++) {
        int k = tid + j * 1024;
        g_cs[k] = (ncs[j] + 1e-5f) / denom * n;
    }
    if (tid == 0) out[O_LOSS] = 0.25f * (g_losssum / 2097152.0f);
}

// ---------------------------------------------------------------------------
// K5: new_ema_w and new_embedding
// ---------------------------------------------------------------------------
__global__ void k_fin2(const float* __restrict__ ema_w, float* __restrict__ out)
{
    int i = blockIdx.x * blockDim.x + threadIdx.x;   // 262144 total
    float nw = 0.99f * ema_w[i] + 0.01f * g_dw[i];
    out[O_NW + i] = nw;
    out[O_NE + i] = __fdiv_rn(nw, g_cs[i >> 6]);
}

// ---------------------------------------------------------------------------
#define SMA_BYTES 57344

extern "C" void kernel_launch(void* const* d_in, const int* in_sizes, int n_in,
                              void* d_out, int out_size)
{
    const float* z      = (const float*)d_in[0];
    const float* emb    = (const float*)d_in[1];
    const float* ema_cs = (const float*)d_in[2];
    const float* ema_w  = (const float*)d_in[3];
    float* out = (float*)d_out;

    cudaFuncSetAttribute(k_passA, cudaFuncAttributeMaxDynamicSharedMemorySize,
                         SMA_BYTES);

    k_prep_a  <<<64, 256>>>(emb);                 // launch 0
    k_prep_b  <<<256, 256>>>(z);                  // launch 1
    k_warm    <<<NROWS / 256, 256>>>(z, emb);     // launch 2
    k_passA   <<<ABLK, 256, SMA_BYTES>>>();       // launch 3  <- profiled
    k_rescreen<<<NROWS / 8, 256>>>(z, emb);       // launch 4
    k_scatter <<<NROWS / 8, 256>>>(z, emb, out);  // launch 5
    k_fin1    <<<1, 1024>>>(ema_cs, out);         // launch 6
    k_fin2    <<<KN * DIM / 256, 256>>>(ema_w, out); // launch 7
}